// round 16
// baseline (speedup 1.0000x reference)
#include <cuda_runtime.h>
#include <cuda_bf16.h>
#include <cstdint>
#include <math.h>

#define Bq   32
#define Sq   512
#define Hq   768
#define Vq   30522
#define NUPD 3
#define MLEN 8
#define Tq   24           // NUPD*MLEN
#define Rq   (Tq*Bq)      // 768 rows (t*32+b)
#define H3   (3*Hq)       // 2304

// ---------------- scratch (device globals; allocation-free) ----------------
__device__ float g_W[Rq*Hq];            // step inputs w_t            2.25 MB
__device__ float g_GI[(size_t)Rq*H3];   // w @ W_ih^T + b_ih          7.1 MB
__device__ float g_H[Rq*Hq];            // GRU hidden per step        2.25 MB
__device__ float g_attnE[(size_t)Rq*Sq];// attention logits           1.5 MB
__device__ float g_attn[(size_t)Rq*Sq]; // attention probs            1.5 MB
__device__ float g_encw[Bq*Sq];         // enc . wgen[2H:3H]
__device__ float g_ctxdot[Rq];
__device__ float g_pgen[Rq];
__device__ float g_logits[(size_t)Rq*Vq]; // vocab logits             93.8 MB
__device__ float g_rmax[Rq];
__device__ float g_rsum[Rq];

// ---------------- build step inputs ----------------
__global__ void k_build_w(const float* __restrict__ dec, const int* __restrict__ teacher,
                          const float* __restrict__ embed)
{
    int t = blockIdx.x, b = blockIdx.y;
    int j = t / MLEN, k = t % MLEN;
    const float* src;
    if (k == 0) {
        src = dec + ((size_t)b*NUPD + j)*Hq;
    } else {
        int tok = teacher[(b*NUPD + j)*MLEN + (k-1)];
        src = embed + (size_t)tok * Hq;
    }
    float* dst = g_W + ((size_t)t*Bq + b)*Hq;
    for (int i = threadIdx.x; i < Hq; i += blockDim.x) dst[i] = src[i];
}

// ---------------- generic tf32 tensor-core GEMM: C[M,N] = A[M,K] @ B[N,K]^T (+bias) ----
__device__ __forceinline__ uint32_t f2tf32(float f) {
    uint32_t u; asm("cvt.rna.tf32.f32 %0, %1;" : "=r"(u) : "f"(f));
    return u;
}

__global__ __launch_bounds__(256) void k_gemm_tf32(
    const float* __restrict__ A, const float* __restrict__ B,
    const float* __restrict__ bias, float* __restrict__ C,
    int M, int N, int K)
{
    __shared__ uint32_t As[128][36];
    __shared__ uint32_t Bs[128][36];
    int tid  = threadIdx.x;
    int lane = tid & 31, warp = tid >> 5;
    int gid  = lane >> 2, tig = lane & 3;
    int wm   = (warp >> 2) * 64;   // 2 warp-rows
    int wn   = (warp & 3) * 32;    // 4 warp-cols
    int bm   = blockIdx.y * 128, bn = blockIdx.x * 128;

    float acc[4][4][4];
#pragma unroll
    for (int a = 0; a < 4; a++)
#pragma unroll
        for (int bb = 0; bb < 4; bb++)
#pragma unroll
            for (int q = 0; q < 4; q++) acc[a][bb][q] = 0.f;

    int lr = tid >> 3;          // 0..31 (row within 32-row group)
    int lc = (tid & 7) * 4;     // 0,4,...,28

    for (int k0 = 0; k0 < K; k0 += 32) {
#pragma unroll
        for (int i = 0; i < 4; i++) {
            int r = i*32 + lr;
            float4 v = *(const float4*)(A + (size_t)(bm + r)*K + k0 + lc);
            As[r][lc+0] = f2tf32(v.x); As[r][lc+1] = f2tf32(v.y);
            As[r][lc+2] = f2tf32(v.z); As[r][lc+3] = f2tf32(v.w);
        }
#pragma unroll
        for (int i = 0; i < 4; i++) {
            int r = i*32 + lr;
            float4 v = make_float4(0.f, 0.f, 0.f, 0.f);
            if (bn + r < N) v = *(const float4*)(B + (size_t)(bn + r)*K + k0 + lc);
            Bs[r][lc+0] = f2tf32(v.x); Bs[r][lc+1] = f2tf32(v.y);
            Bs[r][lc+2] = f2tf32(v.z); Bs[r][lc+3] = f2tf32(v.w);
        }
        __syncthreads();
#pragma unroll
        for (int kk = 0; kk < 32; kk += 8) {
            uint32_t af[4][4], bf[4][2];
#pragma unroll
            for (int im = 0; im < 4; im++) {
                int r0 = wm + im*16 + gid;
                af[im][0] = As[r0    ][kk + tig    ];
                af[im][1] = As[r0 + 8][kk + tig    ];
                af[im][2] = As[r0    ][kk + tig + 4];
                af[im][3] = As[r0 + 8][kk + tig + 4];
            }
#pragma unroll
            for (int in_ = 0; in_ < 4; in_++) {
                int r0 = wn + in_*8 + gid;
                bf[in_][0] = Bs[r0][kk + tig    ];
                bf[in_][1] = Bs[r0][kk + tig + 4];
            }
#pragma unroll
            for (int im = 0; im < 4; im++)
#pragma unroll
                for (int in_ = 0; in_ < 4; in_++) {
                    asm volatile(
                        "mma.sync.aligned.m16n8k8.row.col.f32.tf32.tf32.f32 "
                        "{%0,%1,%2,%3}, {%4,%5,%6,%7}, {%8,%9}, {%0,%1,%2,%3};\n"
                        : "+f"(acc[im][in_][0]), "+f"(acc[im][in_][1]),
                          "+f"(acc[im][in_][2]), "+f"(acc[im][in_][3])
                        : "r"(af[im][0]), "r"(af[im][1]), "r"(af[im][2]), "r"(af[im][3]),
                          "r"(bf[in_][0]), "r"(bf[in_][1]));
                }
        }
        __syncthreads();
    }

#pragma unroll
    for (int im = 0; im < 4; im++) {
        int row = bm + wm + im*16 + gid;
#pragma unroll
        for (int in_ = 0; in_ < 4; in_++) {
            int col = bn + wn + in_*8 + 2*tig;
            float b0 = 0.f, b1 = 0.f;
            if (bias) {
                if (col     < N) b0 = bias[col];
                if (col + 1 < N) b1 = bias[col + 1];
            }
            if (col < N) {
                C[(size_t)row      * N + col] = acc[im][in_][0] + b0;
                C[(size_t)(row + 8)* N + col] = acc[im][in_][2] + b0;
            }
            if (col + 1 < N) {
                C[(size_t)row      * N + col + 1] = acc[im][in_][1] + b1;
                C[(size_t)(row + 8)* N + col + 1] = acc[im][in_][3] + b1;
            }
        }
    }
}

// ---------------- one GRU step (sequential over t) ----------------
__global__ void k_gru_step(const float* __restrict__ hidden0, int t,
                           const float* __restrict__ Whh, const float* __restrict__ bhh)
{
    __shared__ float sh[Hq];
    int b = blockIdx.y;
    int lane = threadIdx.x & 31, warp = threadIdx.x >> 5;
    const float* hp = (t == 0) ? (hidden0 + (size_t)b*Hq)
                               : (g_H + ((size_t)(t-1)*Bq + b)*Hq);
    for (int i = threadIdx.x; i < Hq; i += blockDim.x) sh[i] = hp[i];
    __syncthreads();

    float hv[24];
#pragma unroll
    for (int kk = 0; kk < 24; kk++) hv[kk] = sh[lane + kk*32];

    int cbase = blockIdx.x * 32 + warp * 4;
    const float* gi = g_GI + ((size_t)t*Bq + b)*H3;
    float* ho = g_H + ((size_t)t*Bq + b)*Hq;

    for (int ci = 0; ci < 4; ci++) {
        int c = cbase + ci;
        const float* wr = Whh + (size_t)c          * Hq;
        const float* wz = Whh + (size_t)(c +   Hq) * Hq;
        const float* wn = Whh + (size_t)(c + 2*Hq) * Hq;
        float ar = 0.f, az = 0.f, an = 0.f;
#pragma unroll
        for (int kk = 0; kk < 24; kk++) {
            float h = hv[kk]; int idx = lane + kk*32;
            ar += h * wr[idx]; az += h * wz[idx]; an += h * wn[idx];
        }
#pragma unroll
        for (int off = 16; off; off >>= 1) {
            ar += __shfl_down_sync(0xffffffffu, ar, off);
            az += __shfl_down_sync(0xffffffffu, az, off);
            an += __shfl_down_sync(0xffffffffu, an, off);
        }
        if (lane == 0) {
            float r = 1.f/(1.f + __expf(-(gi[c]        + ar + bhh[c])));
            float z = 1.f/(1.f + __expf(-(gi[c +   Hq] + az + bhh[c +   Hq])));
            float n = tanhf(gi[c + 2*Hq] + r*(an + bhh[c + 2*Hq]));
            ho[c] = (1.f - z)*n + z*sh[c];
        }
    }
}

// ---------------- attention logits + encw (enc . wgen2), batched over t ----------------
__global__ void k_attn(const float* __restrict__ enc, const float* __restrict__ wgen)
{
    __shared__ float shH[12*Hq];   // 12 step hiddens for this batch element
    __shared__ float shW[Hq];
    int stile = blockIdx.x;        // 0..3 (128 s each)
    int b     = blockIdx.y;
    int th    = blockIdx.z;        // 0..1 (t halves)

    for (int tt = 0; tt < 12; tt++)
        for (int i = threadIdx.x; i < Hq; i += 256)
            shH[tt*Hq + i] = g_H[((size_t)(th*12 + tt)*Bq + b)*Hq + i];
    for (int i = threadIdx.x; i < Hq; i += 256) shW[i] = wgen[2*Hq + i];
    __syncthreads();

    int lane = threadIdx.x & 31, warp = threadIdx.x >> 5;
    for (int si = 0; si < 16; si++) {
        int s = stile*128 + warp*16 + si;
        const float* er = enc + ((size_t)b*Sq + s)*Hq;
        float ev[24];
#pragma unroll
        for (int kk = 0; kk < 24; kk++) ev[kk] = er[lane + kk*32];

        if (th == 0) {
            float aw = 0.f;
#pragma unroll
            for (int kk = 0; kk < 24; kk++) aw += ev[kk]*shW[lane + kk*32];
#pragma unroll
            for (int off = 16; off; off >>= 1) aw += __shfl_down_sync(0xffffffffu, aw, off);
            if (lane == 0) g_encw[b*Sq + s] = aw;
        }
        for (int tt = 0; tt < 12; tt++) {
            float a = 0.f;
#pragma unroll
            for (int kk = 0; kk < 24; kk++) a += ev[kk]*shH[tt*Hq + lane + kk*32];
#pragma unroll
            for (int off = 16; off; off >>= 1) a += __shfl_down_sync(0xffffffffu, a, off);
            if (lane == 0)
                g_attnE[((size_t)(th*12 + tt)*Bq + b)*Sq + s] = a;
        }
    }
}

// ---------------- masked softmax over S + ctx.wgen2 dot ----------------
__global__ void k_softmax_attn(const int* __restrict__ x)
{
    __shared__ float red[256];
    int r = blockIdx.x;          // t*32+b
    int b = r & 31;
    int tid = threadIdx.x;
    const float* E = g_attnE + (size_t)r*Sq;
    float e0 = E[tid], e1 = E[tid + 256];
    if (x[b*Sq + tid]       == 0) e0 = -1e9f;
    if (x[b*Sq + tid + 256] == 0) e1 = -1e9f;

    red[tid] = fmaxf(e0, e1); __syncthreads();
    for (int off = 128; off; off >>= 1) {
        if (tid < off) red[tid] = fmaxf(red[tid], red[tid + off]);
        __syncthreads();
    }
    float m = red[0]; __syncthreads();

    float p0 = __expf(e0 - m), p1 = __expf(e1 - m);
    red[tid] = p0 + p1; __syncthreads();
    for (int off = 128; off; off >>= 1) {
        if (tid < off) red[tid] += red[tid + off];
        __syncthreads();
    }
    float inv = 1.f / red[0]; __syncthreads();

    float a0 = p0*inv, a1 = p1*inv;
    g_attn[(size_t)r*Sq + tid]       = a0;
    g_attn[(size_t)r*Sq + tid + 256] = a1;

    red[tid] = a0*g_encw[b*Sq + tid] + a1*g_encw[b*Sq + tid + 256];
    __syncthreads();
    for (int off = 128; off; off >>= 1) {
        if (tid < off) red[tid] += red[tid + off];
        __syncthreads();
    }
    if (tid == 0) g_ctxdot[r] = red[0];
}

// ---------------- p_gen = sigmoid([w,h,ctx] . wgen + b) ----------------
__global__ void k_pgen(const float* __restrict__ wgen, const float* __restrict__ wgen_b)
{
    int lane = threadIdx.x & 31, warp = threadIdx.x >> 5;
    int r = blockIdx.x*8 + warp;
    const float* w = g_W + (size_t)r*Hq;
    const float* h = g_H + (size_t)r*Hq;
    float a = 0.f;
#pragma unroll
    for (int kk = 0; kk < 24; kk++) {
        int i = lane + kk*32;
        a += w[i]*wgen[i] + h[i]*wgen[Hq + i];
    }
#pragma unroll
    for (int off = 16; off; off >>= 1) a += __shfl_down_sync(0xffffffffu, a, off);
    if (lane == 0)
        g_pgen[r] = 1.f/(1.f + __expf(-(a + g_ctxdot[r] + wgen_b[0])));
}

// ---------------- vocab softmax row statistics (online max/sum, one pass) ----------------
__global__ void k_rowstat()
{
    __shared__ float rm[256], rs[256];
    int r = blockIdx.x, tid = threadIdx.x;
    const float* L = g_logits + (size_t)r*Vq;
    float m = -1e30f, s = 0.f;
    for (int v = tid; v < Vq; v += 256) {
        float xv = L[v];
        if (xv > m) { s = s*__expf(m - xv) + 1.f; m = xv; }
        else        { s += __expf(xv - m); }
    }
    rm[tid] = m; rs[tid] = s; __syncthreads();
    for (int off = 128; off; off >>= 1) {
        if (tid < off) {
            float m2 = rm[tid + off], s2 = rs[tid + off];
            float M = fmaxf(rm[tid], m2);
            rs[tid] = rs[tid]*__expf(rm[tid] - M) + s2*__expf(m2 - M);
            rm[tid] = M;
        }
        __syncthreads();
    }
    if (tid == 0) { g_rmax[r] = rm[0]; g_rsum[r] = rs[0]; }
}

// ---------------- final: out = p_gen * softmax(logits) ----------------
__global__ void k_final(float* __restrict__ out)
{
    int r = blockIdx.y;
    int v = blockIdx.x*256 + threadIdx.x;
    if (v >= Vq) return;
    int t = r >> 5, b = r & 31;
    int j = t >> 3, k = t & 7;
    float scale = g_pgen[r] / g_rsum[r];
    float lm    = g_rmax[r];
    float p = __expf(g_logits[(size_t)r*Vq + v] - lm) * scale;
    out[(size_t)((b*NUPD + j)*MLEN + k)*Vq + v] = p;
}

// ---------------- sparse p_ctx scatter: out[.., x[b,s]] += (1-p_gen)*attn ----------------
__global__ void k_scatter(const int* __restrict__ x, float* __restrict__ out)
{
    int idx = blockIdx.x*256 + threadIdx.x;   // r*512 + s
    int r = idx >> 9, s = idx & 511;
    int t = r >> 5, b = r & 31;
    int j = t >> 3, k = t & 7;
    float val = (1.f - g_pgen[r]) * g_attn[(size_t)r*Sq + s];
    int vi = x[b*Sq + s];
    atomicAdd(out + (size_t)((b*NUPD + j)*MLEN + k)*Vq + vi, val);
}

// ---------------- host launch ----------------
extern "C" void kernel_launch(void* const* d_in, const int* in_sizes, int n_in,
                              void* d_out, int out_size)
{
    const int*   x       = (const int*)  d_in[0];
    const float* dec     = (const float*)d_in[1];
    const float* enc     = (const float*)d_in[2];
    const float* hidden  = (const float*)d_in[3];
    const int*   teacher = (const int*)  d_in[4];
    const float* embed   = (const float*)d_in[5];
    const float* w_ih    = (const float*)d_in[6];
    const float* w_hh    = (const float*)d_in[7];
    const float* b_ih    = (const float*)d_in[8];
    const float* b_hh    = (const float*)d_in[9];
    const float* wgen_w  = (const float*)d_in[10];
    const float* wgen_b  = (const float*)d_in[11];
    float* out = (float*)d_out;
    (void)in_sizes; (void)n_in; (void)out_size;

    float *pW, *pGI, *pH, *pLogits;
    cudaGetSymbolAddress((void**)&pW,      g_W);
    cudaGetSymbolAddress((void**)&pGI,     g_GI);
    cudaGetSymbolAddress((void**)&pH,      g_H);
    cudaGetSymbolAddress((void**)&pLogits, g_logits);

    // 1. gather step inputs
    k_build_w<<<dim3(Tq, Bq), 256>>>(dec, teacher, embed);
    // 2. GI = W @ W_ih^T + b_ih   (768 x 2304 x 768)
    k_gemm_tf32<<<dim3(H3/128, Rq/128), 256>>>(pW, w_ih, b_ih, pGI, Rq, H3, Hq);
    // 3. sequential GRU chain (only truly sequential part)
    for (int t = 0; t < Tq; t++)
        k_gru_step<<<dim3(24, Bq), 256>>>(hidden, t, w_hh, b_hh);
    // 4. batched attention logits + encw
    k_attn<<<dim3(4, Bq, 2), 256>>>(enc, wgen_w);
    // 5. masked softmax over S + context dot
    k_softmax_attn<<<Rq, 256>>>(x);
    // 6. p_gen
    k_pgen<<<Rq/8, 256>>>(wgen_w, wgen_b);
    // 7. vocab logits GEMM (768 x 30522 x 768, tf32 tensor cores)
    k_gemm_tf32<<<dim3((Vq + 127)/128, Rq/128), 256>>>(pH, embed, nullptr, pLogits, Rq, Vq, Hq);
    // 8. softmax stats over V
    k_rowstat<<<Rq, 256>>>();
    // 9. dense output = p_gen * softmax(logits)
    k_final<<<dim3((Vq + 255)/256, Rq), 256>>>(out);
    // 10. sparse pointer distribution
    k_scatter<<<(Rq*Sq)/256, 256>>>(x, out);
}